// round 17
// baseline (speedup 1.0000x reference)
#include <cuda_runtime.h>
#include <cuda_bf16.h>
#include <cstdint>

typedef unsigned int u32; typedef unsigned short u16;

// AttentionMV B=T=1024, E=128. mma.sync bf16 3-pass split. R17.
// WARP SPECIALIZATION: 512 threads. Warps 0-7 = producers (GEMM1+tanh+split ->
// u-frag SMEM ring). Warps 8-15 = consumers (GEMM2, pre accumulators, vT via
// cp.async). Named-barrier full/empty handoff, double-buffered UF.
//  GEMM1 (per 64-t tile): D1[f][t] = sum_e WT[f][e]*m[t][e]
//  u = tanh(D1+b); GEMM2: pre[e][f] += sum_t vT[e][t]*u[t][f]

constexpr int NT = 512;
constexpr u32 WFH = 0;           // W frags 64KB
constexpr u32 WFL = 32768;
constexpr u32 MFH = 65536;       // m frags 32KB (producer-private)
constexpr u32 MFL = 81920;
constexpr u32 UF0H = 98304;      // u-frag slot0: hi 16K
constexpr u32 UF0L = 114688;     //               lo 16K
constexpr u32 UF1H = 131072;     // u-frag slot1
constexpr u32 UF1L = 147456;
constexpr u32 VT0 = 163840;      // vT slot0 (hi 16K + lo 16K)
constexpr u32 VT1 = 196608;      // vT slot1
constexpr u32 SMEM_BYTES = 229376;
// epilogue aliases (dead regions)
constexpr u32 P_OFF = 0, EX_OFF = 98304, SP_OFF = 196608, CF_OFF = 200704;

__device__ u16 g_vtFH[131072];   // vT A-frag images, 16KB per 64-t tile
__device__ u16 g_vtFL[131072];
__device__ float g_biasF[131072];

__device__ __forceinline__ float fast_tanh(float x){
    float e = __expf(2.0f*x);
    return 1.0f - __fdividef(2.0f, e+1.0f);
}
__device__ __forceinline__ float trunc_hi(float x){
    return __uint_as_float(__float_as_uint(x) & 0xffff0000u);
}
__device__ __forceinline__ u32 cvt_bf16x2(float hiArg, float loArg){
    u32 d; asm("cvt.rn.bf16x2.f32 %0, %1, %2;" : "=r"(d) : "f"(hiArg), "f"(loArg));
    return d;
}
__device__ __forceinline__ void mma16816(float* d, u32 a0,u32 a1,u32 a2,u32 a3,
                                         u32 b0,u32 b1){
    asm volatile("mma.sync.aligned.m16n8k16.row.col.f32.bf16.bf16.f32 "
        "{%0,%1,%2,%3}, {%4,%5,%6,%7}, {%8,%9}, {%0,%1,%2,%3};"
        : "+f"(d[0]),"+f"(d[1]),"+f"(d[2]),"+f"(d[3])
        : "r"(a0),"r"(a1),"r"(a2),"r"(a3),"r"(b0),"r"(b1));
}
__device__ __forceinline__ u32 smem_u32(const void* p){
    u32 a; asm("{ .reg .u64 t; cvta.to.shared.u64 t, %1; cvt.u32.u64 %0, t; }"
               : "=r"(a) : "l"(p));
    return a;
}
__device__ __forceinline__ void cp16(u32 dst, const void* src){
    asm volatile("cp.async.ca.shared.global [%0], [%1], 16;" :: "r"(dst), "l"(src));
}
#define BARS(id,n) asm volatile("bar.sync %0, %1;" :: "r"(id), "r"(n) : "memory")
#define BARA(id,n) asm volatile("bar.arrive %0, %1;" :: "r"(id), "r"(n) : "memory")

// vT A-frag prep (verified R9 layout)
__global__ void vt_prep(const float* __restrict__ gv){
    int t = blockIdx.x, e = threadIdx.x;
    float x = gv[t*128 + e];
    u16 hi = (u16)(__float_as_uint(x) >> 16);
    u16 lo = __bfloat16_as_ushort(__float2bfloat16(x - trunc_hi(x)));
    int tile = t>>6, s = (t>>4)&3, tr = t&15;
    int kh = tr>>3, rs = (tr&7)>>1, byt = tr&1;
    int i = e>>4, eq = e&15, rh = eq>>3, q = eq&7;
    int reg = rh + 2*kh, lane = q*4 + rs;
    int idx = ((tile*32 + i*4 + s)*32 + lane)*8 + reg*2 + byt;
    g_vtFH[idx] = hi; g_vtFL[idx] = lo;
}

// bias packed in accumulator-fragment order (verified R12/R16 mapping)
__global__ void bias_prep(const float* __restrict__ gb){
    int idx = blockIdx.x*256 + threadIdx.x;
    int c = idx&3, nb=(idx>>2)&7, lane=(idx>>5)&31, w=(idx>>10)&7, tile=idx>>13;
    int q=lane>>2, r2=(lane&3)*2;
    int t = tile*64 + nb*8 + r2 + (c&1);
    int f = w*16 + q + 8*(c>>1);
    g_biasF[idx] = gb[t*128+f];
}

__global__ __launch_bounds__(NT,1)
void attn_mma(const float* __restrict__ gm, const float* __restrict__ gW,
              float* __restrict__ gout)
{
    extern __shared__ char sm[];
    const u32 sbase = smem_u32(sm);
    const int tid=threadIdx.x, lane=tid&31, w=tid>>5, bb=blockIdx.x;
    const int q=lane>>2, r2=(lane&3)*2;
    const float* Wb = gW + (size_t)bb*16384;
    const float4* mb4 = (const float4*)(gm + (size_t)bb*131072);

    // ---- W -> A-frag layout (all 512 threads)
    for (int it=0; it<32; it++){
        int idx = it*NT + tid;
        int e = idx>>7, f = idx&127;
        float x = __ldg(Wb + idx);
        u16 hi = (u16)(__float_as_uint(x) >> 16);
        u16 lo = __bfloat16_as_ushort(__float2bfloat16(x - trunc_hi(x)));
        int w2=f>>4, fr=f&15, rh=fr>>3, qq=fr&7;
        int ks=e>>4, er=e&15, kh=er>>3, rs=(er&7)>>1, byt=er&1;
        u32 off = (u32)(((w2*8+ks)*32 + qq*4 + rs)*16 + (rh + 2*kh)*4 + byt*2);
        *(u16*)(sm + WFH + off) = hi;
        *(u16*)(sm + WFL + off) = lo;
    }

    float s4[4]={0,0,0,0};          // producer colsum partials

    if (w < 8){
        // =================== PRODUCER ===================
        const int m_ks = lane>>2, m_r = (lane>>1)&1, m_lsub = (lane&1)*2;
        float4 mreg[8];
        auto msplit = [&](){
            #pragma unroll
            for (int j=0;j<8;j++){
                float4 x = mreg[j];
                s4[0]+=x.x; s4[1]+=x.y; s4[2]+=x.z; s4[3]+=x.w;
                u32 hA = __byte_perm(__float_as_uint(x.x), __float_as_uint(x.y), 0x7632);
                u32 hB = __byte_perm(__float_as_uint(x.z), __float_as_uint(x.w), 0x7632);
                float l0 = x.x - trunc_hi(x.x), l1 = x.y - trunc_hi(x.y);
                float l2 = x.z - trunc_hi(x.z), l3 = x.w - trunc_hi(x.w);
                u32 lA = cvt_bf16x2(l1, l0), lB = cvt_bf16x2(l3, l2);
                int l  = w*4 + m_lsub;
                u32 base = (u32)((j*8 + m_ks) << 8);
                u32 pA = (u32)((l*2     + m_r + m_ks*8) & 63)*4;
                u32 pB = (u32)(((l+1)*2 + m_r + m_ks*8) & 63)*4;
                *(u32*)(sm + MFH + base + pA) = hA;
                *(u32*)(sm + MFH + base + pB) = hB;
                *(u32*)(sm + MFL + base + pA) = lA;
                *(u32*)(sm + MFL + base + pB) = lB;
            }
        };
        // prologue: tile0 frags, preload tile1 (m loads use producer tid 0..255)
        #pragma unroll
        for (int j=0;j<8;j++) mreg[j] = __ldg(mb4 + j*256 + tid);
        msplit();
        #pragma unroll
        for (int j=0;j<8;j++) mreg[j] = __ldg(mb4 + 2048 + j*256 + tid);
        __syncthreads();   // WF + MF(0) visible; consumer primed

        const float4* bfr = (const float4*)g_biasF;
        for (int k=0;k<16;k++){
            // bias prefetch (frag-packed, consumed after GEMM1)
            float4 bl4[8];
            #pragma unroll
            for (int nb=0;nb<8;nb++)
                bl4[nb] = __ldg(bfr + ((size_t)(k*8+w)*32+lane)*8 + nb);

            // ---- GEMM1 (R9 verbatim)
            float d1[8][4];
            #pragma unroll
            for (int nb=0;nb<8;nb++){ d1[nb][0]=0;d1[nb][1]=0;d1[nb][2]=0;d1[nb][3]=0; }
            #pragma unroll
            for (int ks=0;ks<8;ks++){
                uint4 ahv = *(const uint4*)(sm + WFH + (u32)(((w*8+ks)*32+lane)*16));
                uint4 alv = *(const uint4*)(sm + WFL + (u32)(((w*8+ks)*32+lane)*16));
                u32 bh[8][2], bl[8][2];
                u32 bpos = (u32)(((lane*2) + ks*8) & 63)*4;
                #pragma unroll
                for (int nb=0;nb<8;nb++){
                    uint2 t2 = *(const uint2*)(sm + MFH + (u32)((nb*8+ks)<<8) + bpos);
                    bh[nb][0]=t2.x; bh[nb][1]=t2.y;
                    uint2 t3 = *(const uint2*)(sm + MFL + (u32)((nb*8+ks)<<8) + bpos);
                    bl[nb][0]=t3.x; bl[nb][1]=t3.y;
                }
                #pragma unroll
                for (int nb=0;nb<8;nb++)
                    mma16816(d1[nb], ahv.x,ahv.y,ahv.z,ahv.w, bh[nb][0],bh[nb][1]);
                #pragma unroll
                for (int nb=0;nb<8;nb++)
                    mma16816(d1[nb], ahv.x,ahv.y,ahv.z,ahv.w, bl[nb][0],bl[nb][1]);
                #pragma unroll
                for (int nb=0;nb<8;nb++)
                    mma16816(d1[nb], alv.x,alv.y,alv.z,alv.w, bh[nb][0],bh[nb][1]);
            }

            // ---- bias + tanh + split
            u32 uh[8][2], ul[8][2];
            #pragma unroll
            for (int nb=0;nb<8;nb++){
                float u0=fast_tanh(d1[nb][0]+bl4[nb].x);
                float u1=fast_tanh(d1[nb][1]+bl4[nb].y);
                float u2=fast_tanh(d1[nb][2]+bl4[nb].z);
                float u3=fast_tanh(d1[nb][3]+bl4[nb].w);
                uh[nb][0] = __byte_perm(__float_as_uint(u0), __float_as_uint(u1), 0x7632);
                uh[nb][1] = __byte_perm(__float_as_uint(u2), __float_as_uint(u3), 0x7632);
                ul[nb][0] = cvt_bf16x2(u1 - trunc_hi(u1), u0 - trunc_hi(u0));
                ul[nb][1] = cvt_bf16x2(u3 - trunc_hi(u3), u2 - trunc_hi(u2));
            }

            // ---- wait slot empty, store u-frags, signal full
            BARS(1+(k&1), 512);
            {
                u32 ufH = (k&1) ? UF1H : UF0H;
                u32 ufL = (k&1) ? UF1L : UF0L;
                #pragma unroll
                for (int s=0;s<4;s++)
                    #pragma unroll
                    for (int fb=0;fb<2;fb++){
                        u32 off = (u32)(((w*4+s)*2+fb)*256) + lane*8;
                        *(uint2*)(sm + ufH + off) = make_uint2(uh[2*s][fb], uh[2*s+1][fb]);
                        *(uint2*)(sm + ufL + off) = make_uint2(ul[2*s][fb], ul[2*s+1][fb]);
                    }
            }
            BARA(3+(k&1), 512);

            // ---- next m-frags (producer-internal sync around MF reuse)
            BARS(5, 256);
            if (k<15){
                msplit();
                if (k<14){
                    #pragma unroll
                    for (int j=0;j<8;j++)
                        mreg[j] = __ldg(mb4 + (size_t)(k+2)*2048 + j*256 + tid);
                }
            }
            BARS(5, 256);
        }
    } else {
        // =================== CONSUMER ===================
        const int wc = w - 8, ct = tid & 255;
        auto cpvt = [&](int t, int slot){
            u32 dst = slot ? VT1 : VT0;
            const char* sH = (const char*)g_vtFH + (size_t)t*16384;
            const char* sL = (const char*)g_vtFL + (size_t)t*16384;
            #pragma unroll
            for (int k2=0;k2<4;k2++){
                cp16(sbase + dst + ct*64 + k2*16,         sH + ct*64 + k2*16);
                cp16(sbase + dst + 16384 + ct*64 + k2*16, sL + ct*64 + k2*16);
            }
        };
        cpvt(0, 0);
        asm volatile("cp.async.commit_group;");
        BARA(1, 512);   // prime EMPTY slot0
        BARA(2, 512);   // prime EMPTY slot1

        float pre[8][2][4];
        #pragma unroll
        for (int i=0;i<8;i++)
            #pragma unroll
            for (int fb=0;fb<2;fb++)
                #pragma unroll
                for (int j2=0;j2<4;j2++) pre[i][fb][j2]=0.f;

        __syncthreads();

        for (int k=0;k<16;k++){
            BARS(6, 256);                        // all consumers done with prev GEMM2
            if (k<15) cpvt(k+1, (k+1)&1);
            asm volatile("cp.async.commit_group;");
            asm volatile("cp.async.wait_group 1;");   // VT(k) landed (own slices)
            BARS(6, 256);                        // VT(k) visible to all consumers
            BARS(3+(k&1), 512);                  // u-frags(k) full

            const u32 VTp = (k&1) ? VT1 : VT0;
            const u32 ufH = (k&1) ? UF1H : UF0H;
            const u32 ufL = (k&1) ? UF1L : UF0L;
            #pragma unroll
            for (int s=0;s<4;s++){
                uint2 bH[2], bL[2];
                #pragma unroll
                for (int fb=0;fb<2;fb++){
                    u32 off = (u32)(((wc*4+s)*2+fb)*256) + lane*8;
                    bH[fb] = *(const uint2*)(sm + ufH + off);
                    bL[fb] = *(const uint2*)(sm + ufL + off);
                }
                #pragma unroll
                for (int iq=0;iq<2;iq++){
                    u32 ah[4][4], al[4][4];
                    #pragma unroll
                    for (int ii=0;ii<4;ii++){
                        int i = iq*4+ii;
                        uint4 a4 = *(const uint4*)(sm + VTp + (u32)(((i*4+s)*32+lane)*16));
                        ah[ii][0]=a4.x; ah[ii][1]=a4.y; ah[ii][2]=a4.z; ah[ii][3]=a4.w;
                        uint4 a5 = *(const uint4*)(sm + VTp + 16384 + (u32)(((i*4+s)*32+lane)*16));
                        al[ii][0]=a5.x; al[ii][1]=a5.y; al[ii][2]=a5.z; al[ii][3]=a5.w;
                    }
                    #pragma unroll
                    for (int ii=0;ii<4;ii++)
                        #pragma unroll
                        for (int fb=0;fb<2;fb++)
                            mma16816(pre[iq*4+ii][fb], ah[ii][0],ah[ii][1],ah[ii][2],ah[ii][3],
                                     bH[fb].x, bH[fb].y);
                    #pragma unroll
                    for (int ii=0;ii<4;ii++)
                        #pragma unroll
                        for (int fb=0;fb<2;fb++)
                            mma16816(pre[iq*4+ii][fb], ah[ii][0],ah[ii][1],ah[ii][2],ah[ii][3],
                                     bL[fb].x, bL[fb].y);
                    #pragma unroll
                    for (int ii=0;ii<4;ii++)
                        #pragma unroll
                        for (int fb=0;fb<2;fb++)
                            mma16816(pre[iq*4+ii][fb], al[ii][0],al[ii][1],al[ii][2],al[ii][3],
                                     bH[fb].x, bH[fb].y);
                }
            }
            BARA(1+(k&1), 512);                  // slot empty
        }

        // park pre for epilogue (written after the full-CTA sync below)
        __syncthreads();
        float* P = (float*)(sm + P_OFF);
        #pragma unroll
        for (int i=0;i<8;i++)
            #pragma unroll
            for (int fb=0;fb<2;fb++){
                int e0 = i*16+q, f0 = wc*16+fb*8+r2;
                P[e0*132+f0]       = pre[i][fb][0];
                P[e0*132+f0+1]     = pre[i][fb][1];
                P[(e0+8)*132+f0]   = pre[i][fb][2];
                P[(e0+8)*132+f0+1] = pre[i][fb][3];
            }
    }

    if (w < 8){
        __syncthreads();   // pairs with consumer's pre-epilogue sync
        float* SP=(float*)(sm+SP_OFF);
        *(float4*)(SP + w*128 + lane*4) = make_float4(s4[0],s4[1],s4[2],s4[3]);
    }
    __syncthreads();       // P + SP complete

    float* P  = (float*)(sm + P_OFF);
    float* SP = (float*)(sm + SP_OFF);
    float* EX = (float*)(sm + EX_OFF);
    float* CF = (float*)(sm + CF_OFF);
    if (tid<128){
        int e=tid;
        float ss=0;
        #pragma unroll
        for (int ww=0;ww<8;ww++) ss+=SP[ww*128+e];
        float mx=-1e30f;
        #pragma unroll 8
        for (int f=0;f<128;f++) mx=fmaxf(mx,P[e*132+f]);
        float sum=0;
        #pragma unroll 4
        for (int f=0;f<128;f++){
            float ex=__expf(P[e*132+f]-mx);
            sum+=ex; EX[f*132+e]=ex;
        }
        CF[e]=ss*__fdividef(1.f,sum);
    }
    __syncthreads();
    if (tid<128){
        int f=tid; float acc=0;
        #pragma unroll 8
        for (int e=0;e<128;e++) acc=fmaf(CF[e],EX[f*132+e],acc);
        gout[(size_t)bb*128+f]=acc;
    }
}

extern "C" void kernel_launch(void* const* d_in, const int* in_sizes, int n_in,
                              void* d_out, int out_size) {
    const float* m = (const float*)d_in[0];
    const float* v = (const float*)d_in[1];
    const float* W = (const float*)d_in[2];
    const float* b = (const float*)d_in[3];
    float* out = (float*)d_out;

    vt_prep<<<1024, 128>>>(v);
    bias_prep<<<512, 256>>>(b);
    cudaFuncSetAttribute(attn_mma, cudaFuncAttributeMaxDynamicSharedMemorySize,
                         (int)SMEM_BYTES);
    attn_mma<<<1024, NT, SMEM_BYTES>>>(m, W, out);
}